// round 9
// baseline (speedup 1.0000x reference)
#include <cuda_runtime.h>
#include <cuda_bf16.h>
#include <stdint.h>
#include <math.h>

// ============================================================================
// Shapes: B=8, M=256, E=128, K=16, H=1024, A=256, R=1024, RMS=512
//   P = mention @ Wvu^T (Wv/Wu rows interleaved), score fused into epilogue
//   E = softmax-pooled mention rows
//   Cg = RMT@RMT^T (split-K4) ; M2 = Wr Cg + br(x)colsum (split-K2)
//   WT = Wo2 M2^T + Wo1 ; out = E WT^T + bo
// GEMMs: C = A[M,K]*B[N,K]^T via mma.m16n8k16.bf16, bf16x3 hi/lo split.
// Block 128x64, BK=64, 512 threads = 16 warps: warps 0-7 do k-steps {0,1},
// warps 8-15 do k-steps {2,3} (intra-CTA split-K), smem reduction at end.
// Warp tile stays 32x32 (same MMA:LDSM ratio as the 98.5us build).
// ============================================================================

__device__ __nv_bfloat16 g_mhi[2048*1024], g_mlo[2048*1024];
__device__ __nv_bfloat16 g_wvuh[512*1024], g_wvul[512*1024];   // interleaved v/u rows
__device__ __nv_bfloat16 g_rmth[512*1024], g_rmtl[512*1024];
__device__ __nv_bfloat16 g_wrh[1024*512],  g_wrl[1024*512];
__device__ __nv_bfloat16 g_wo2h[1024*512], g_wo2l[1024*512];
__device__ __nv_bfloat16 g_cgh[512*512],   g_cgl[512*512];
__device__ __nv_bfloat16 g_m2h[1024*512],  g_m2l[1024*512];
__device__ __nv_bfloat16 g_wth[1024*1024], g_wtl[1024*1024];
__device__ __nv_bfloat16 g_eh[1024*1024],  g_el[1024*1024];
__device__ float g_P[2048*512];      // split-K partial arena
__device__ float g_g16[16*2048];     // score column-block partials
__device__ float g_part[8*512];

static cudaStream_t s_rel;
static cudaEvent_t  e_fork, e_rel;
static struct StreamInit {
    StreamInit() {
        cudaStreamCreateWithFlags(&s_rel, cudaStreamNonBlocking);
        cudaEventCreateWithFlags(&e_fork, cudaEventDisableTiming);
        cudaEventCreateWithFlags(&e_rel,  cudaEventDisableTiming);
    }
} s_init;

__device__ __forceinline__ uint32_t smem_u32(const void* p) {
    uint32_t a;
    asm("{ .reg .u64 t; cvta.to.shared.u64 t, %1; cvt.u32.u64 %0, t; }" : "=r"(a) : "l"(p));
    return a;
}

#define CP16(dst, src) \
    asm volatile("cp.async.cg.shared.global [%0], [%1], 16;" :: "r"(dst), "l"(src))
#define CP_COMMIT() asm volatile("cp.async.commit_group;" ::: "memory")
#define CP_WAIT(n)  asm volatile("cp.async.wait_group %0;" :: "n"(n) : "memory")

#define LDSM4(r0, r1, r2, r3, addr) \
    asm volatile("ldmatrix.sync.aligned.m8n8.x4.shared.b16 {%0,%1,%2,%3}, [%4];" \
        : "=r"(r0), "=r"(r1), "=r"(r2), "=r"(r3) : "r"(addr))

__device__ __forceinline__ void mma16816(float* c, const uint32_t* a, const uint32_t* b) {
    asm volatile("mma.sync.aligned.m16n8k16.row.col.f32.bf16.bf16.f32 "
        "{%0,%1,%2,%3}, {%4,%5,%6,%7}, {%8,%9}, {%0,%1,%2,%3};"
        : "+f"(c[0]), "+f"(c[1]), "+f"(c[2]), "+f"(c[3])
        : "r"(a[0]), "r"(a[1]), "r"(a[2]), "r"(a[3]), "r"(b[0]), "r"(b[1]));
}

// BK=64: rows 128B, padded to 144B (rows start at bank 4r mod 32 -> conflict-free)
#define TSTRIDE 144
#define ATILEB  (128 * TSTRIDE)
#define BTILEB  (64 * TSTRIDE)
#define STAGEB  (2 * ATILEB + 2 * BTILEB)  // 55296
#define NSTAGE  3
#define SMEM_GEMM (NSTAGE * STAGEB)        // 165888

#define OFF_AH 0
#define OFF_AL ATILEB
#define OFF_BH (2 * ATILEB)
#define OFF_BL (2 * ATILEB + BTILEB)

enum { EP_SCORE = 0, EP_PART = 1, EP_WEFFT = 2, EP_OUT = 3 };

// 512-thread tile loads
__device__ __forceinline__ void issue_tileA(uint32_t sdst,
        const __nv_bfloat16* __restrict__ G, int ld, int r0, int k0, int t) {
#pragma unroll
    for (int q = 0; q < 2; q++) {
        const int idx = t + (q << 9);
        const int r = idx >> 3, ch = idx & 7;
        CP16(sdst + r * TSTRIDE + ch * 16,
             G + (size_t)(r0 + r) * ld + k0 + ch * 8);
    }
}
__device__ __forceinline__ void issue_tileB(uint32_t sdst,
        const __nv_bfloat16* __restrict__ G, int ld, int r0, int k0, int t) {
    const int r = t >> 3, ch = t & 7;
    CP16(sdst + r * TSTRIDE + ch * 16,
         G + (size_t)(r0 + r) * ld + k0 + ch * 8);
}

__device__ __forceinline__ void store_hilo(__nv_bfloat16* Ch, __nv_bfloat16* Cl,
        int ldc, int row, int col, float v0, float v1) {
    __nv_bfloat16 h0 = __float2bfloat16(v0);
    __nv_bfloat16 h1 = __float2bfloat16(v1);
    __nv_bfloat162 hp; hp.x = h0; hp.y = h1;
    __nv_bfloat162 lp;
    lp.x = __float2bfloat16(v0 - __bfloat162float(h0));
    lp.y = __float2bfloat16(v1 - __bfloat162float(h1));
    *(__nv_bfloat162*)(Ch + (size_t)row * ldc + col) = hp;
    *(__nv_bfloat162*)(Cl + (size_t)row * ldc + col) = lp;
}

template <int EPI>
__global__ __launch_bounds__(512, 1)
void gemm_bf16x3(
    const __nv_bfloat16* __restrict__ Ah, const __nv_bfloat16* __restrict__ Al, int lda,
    const __nv_bfloat16* __restrict__ Bh, const __nv_bfloat16* __restrict__ Bl, int ldb,
    int Kper,
    float* __restrict__ Cf, __nv_bfloat16* __restrict__ Ch, __nv_bfloat16* __restrict__ Cl,
    int ldc,
    const float* __restrict__ aux1, const float* __restrict__ aux2,
    const float* __restrict__ aux3, int auxld, size_t partStride)
{
    extern __shared__ __align__(128) char sm[];
    const uint32_t sbase = smem_u32(sm);
    const int t = threadIdx.x, lane = t & 31, wid = t >> 5;
    const int w7 = wid & 7, khalf = wid >> 3;     // khalf: which k-step pair
    const int wm = w7 >> 1, wn = w7 & 1;          // 4x2 grid, warp tile 32x32
    const int m0 = blockIdx.y * 128, n0 = blockIdx.x * 64;
    const int Koff = blockIdx.z * Kper;
    const int nch = Kper >> 6;
    const uint32_t kbase = (uint32_t)khalf * 64;  // byte offset of this half's k-steps

    float acc[2][4][4] = {};
    uint32_t fAh[2][2][4], fAl[2][2][4], fBh[2][4][2], fBl[2][4][2];

#pragma unroll
    for (int c = 0; c < 2; c++) {
        const uint32_t sb = sbase + c * STAGEB;
        issue_tileA(sb + OFF_AH, Ah, lda, m0, Koff + c * 64, t);
        issue_tileA(sb + OFF_AL, Al, lda, m0, Koff + c * 64, t);
        issue_tileB(sb + OFF_BH, Bh, ldb, n0, Koff + c * 64, t);
        issue_tileB(sb + OFF_BL, Bl, ldb, n0, Koff + c * 64, t);
        CP_COMMIT();
    }

    const uint32_t a_off = (uint32_t)((lane & 15) * TSTRIDE + (lane >> 4) * 16)
                         + (uint32_t)(wm * 32 * TSTRIDE);
    const uint32_t b_off = (uint32_t)(((lane & 7) + ((lane >> 4) & 1) * 8) * TSTRIDE
                                      + ((lane >> 3) & 1) * 16)
                         + (uint32_t)(wn * 32 * TSTRIDE);

    for (int c = 0; c < nch; c++) {
        CP_WAIT(1);
        __syncthreads();
        if (c + 2 < nch) {
            const uint32_t sb = sbase + ((c + 2) % NSTAGE) * STAGEB;
            issue_tileA(sb + OFF_AH, Ah, lda, m0, Koff + (c + 2) * 64, t);
            issue_tileA(sb + OFF_AL, Al, lda, m0, Koff + (c + 2) * 64, t);
            issue_tileB(sb + OFF_BH, Bh, ldb, n0, Koff + (c + 2) * 64, t);
            issue_tileB(sb + OFF_BL, Bl, ldb, n0, Koff + (c + 2) * 64, t);
        }
        CP_COMMIT();

        const uint32_t sb = sbase + (c % NSTAGE) * STAGEB;
        const uint32_t sAh = sb + OFF_AH + a_off;
        const uint32_t sAl = sb + OFF_AL + a_off;
        const uint32_t sBh = sb + OFF_BH + b_off;
        const uint32_t sBl = sb + OFF_BL + b_off;

        // this warp's first k-step fragments (kbase)
#pragma unroll
        for (int mi = 0; mi < 2; mi++) {
            const uint32_t ao = mi * 16 * TSTRIDE + kbase;
            LDSM4(fAh[0][mi][0], fAh[0][mi][1], fAh[0][mi][2], fAh[0][mi][3], sAh + ao);
            LDSM4(fAl[0][mi][0], fAl[0][mi][1], fAl[0][mi][2], fAl[0][mi][3], sAl + ao);
        }
#pragma unroll
        for (int np = 0; np < 2; np++) {
            const uint32_t bo = np * 16 * TSTRIDE + kbase;
            LDSM4(fBh[0][np*2][0], fBh[0][np*2][1], fBh[0][np*2+1][0], fBh[0][np*2+1][1], sBh + bo);
            LDSM4(fBl[0][np*2][0], fBl[0][np*2][1], fBl[0][np*2+1][0], fBl[0][np*2+1][1], sBl + bo);
        }

#pragma unroll
        for (int ks = 0; ks < 2; ks++) {
            if (ks == 0) {   // prefetch second k-step fragments before MMAs
                const uint32_t ko = kbase + 32;
#pragma unroll
                for (int mi = 0; mi < 2; mi++) {
                    const uint32_t ao = mi * 16 * TSTRIDE + ko;
                    LDSM4(fAh[1][mi][0], fAh[1][mi][1], fAh[1][mi][2], fAh[1][mi][3], sAh + ao);
                    LDSM4(fAl[1][mi][0], fAl[1][mi][1], fAl[1][mi][2], fAl[1][mi][3], sAl + ao);
                }
#pragma unroll
                for (int np = 0; np < 2; np++) {
                    const uint32_t bo = np * 16 * TSTRIDE + ko;
                    LDSM4(fBh[1][np*2][0], fBh[1][np*2][1], fBh[1][np*2+1][0], fBh[1][np*2+1][1], sBh + bo);
                    LDSM4(fBl[1][np*2][0], fBl[1][np*2][1], fBl[1][np*2+1][0], fBl[1][np*2+1][1], sBl + bo);
                }
            }
            // term-outer ordering: 8 independent MMAs between same-acc updates
#pragma unroll
            for (int mi = 0; mi < 2; mi++)
#pragma unroll
                for (int nj = 0; nj < 4; nj++)
                    mma16816(acc[mi][nj], fAh[ks][mi], fBh[ks][nj]);
#pragma unroll
            for (int mi = 0; mi < 2; mi++)
#pragma unroll
                for (int nj = 0; nj < 4; nj++)
                    mma16816(acc[mi][nj], fAh[ks][mi], fBl[ks][nj]);
#pragma unroll
            for (int mi = 0; mi < 2; mi++)
#pragma unroll
                for (int nj = 0; nj < 4; nj++)
                    mma16816(acc[mi][nj], fAl[ks][mi], fBh[ks][nj]);
        }
    }

    // ---- intra-CTA split-K reduction: upper warps -> smem -> lower warps ----
    __syncthreads();                // stage buffers dead now
    float* red = (float*)sm;        // layout [32][257] floats, conflict-free
    const int halfT = t & 255;
    if (khalf == 1) {
        int i = 0;
#pragma unroll
        for (int mi = 0; mi < 2; mi++)
#pragma unroll
            for (int nj = 0; nj < 4; nj++)
#pragma unroll
                for (int x = 0; x < 4; x++)
                    red[(i++) * 257 + halfT] = acc[mi][nj][x];
    }
    __syncthreads();
    if (khalf == 1) return;         // no barriers below
    {
        int i = 0;
#pragma unroll
        for (int mi = 0; mi < 2; mi++)
#pragma unroll
            for (int nj = 0; nj < 4; nj++)
#pragma unroll
                for (int x = 0; x < 4; x++)
                    acc[mi][nj][x] += red[(i++) * 257 + halfT];
    }

    const int g = lane >> 2, tq = lane & 3;

    if (EPI == EP_SCORE) {
        float pl[2];
#pragma unroll
        for (int mi = 0; mi < 2; mi++) {
            float p0 = 0.f, p8 = 0.f;
#pragma unroll
            for (int nj = 0; nj < 4; nj++) {
                const int C = n0 + wn * 32 + nj * 8 + tq * 2;
                const int a = C >> 1;
                const float bva = aux1[a], bua = aux2[a], waa = aux3[a];
                {
                    float v = tanhf(acc[mi][nj][0] + bva);
                    float u = acc[mi][nj][1] + bua;
                    u = 1.f / (1.f + __expf(-u));
                    p0 = fmaf(v * u, waa, p0);
                }
                {
                    float v = tanhf(acc[mi][nj][2] + bva);
                    float u = acc[mi][nj][3] + bua;
                    u = 1.f / (1.f + __expf(-u));
                    p8 = fmaf(v * u, waa, p8);
                }
            }
            pl[0] = p0; pl[1] = p8;
#pragma unroll
            for (int o = 1; o <= 2; o <<= 1) {
                pl[0] += __shfl_xor_sync(0xffffffffu, pl[0], o);
                pl[1] += __shfl_xor_sync(0xffffffffu, pl[1], o);
            }
            if (tq == 0) {
                const int cb = blockIdx.x * 2 + wn;
                const int row = m0 + wm * 32 + mi * 16 + g;
                Cf[(size_t)cb * 2048 + row] = pl[0];
                Cf[(size_t)cb * 2048 + row + 8] = pl[1];
            }
        }
        return;
    }

#pragma unroll
    for (int mi = 0; mi < 2; mi++) {
#pragma unroll
        for (int nj = 0; nj < 4; nj++) {
            const int row = m0 + wm * 32 + mi * 16 + g;
            const int col = n0 + wn * 32 + nj * 8 + tq * 2;
            float v00 = acc[mi][nj][0], v01 = acc[mi][nj][1];
            float v10 = acc[mi][nj][2], v11 = acc[mi][nj][3];
            if (EPI == EP_PART) {
                float* dst = Cf + blockIdx.z * partStride;
                *(float2*)(dst + (size_t)row * ldc + col) = make_float2(v00, v01);
                *(float2*)(dst + (size_t)(row + 8) * ldc + col) = make_float2(v10, v11);
            } else if (EPI == EP_OUT) {
                const float b0 = aux1[col], b1 = aux1[col + 1];
                *(float2*)(Cf + (size_t)row * ldc + col) = make_float2(v00 + b0, v01 + b1);
                *(float2*)(Cf + (size_t)(row + 8) * ldc + col) = make_float2(v10 + b0, v11 + b1);
            } else {  // EP_WEFFT
                v00 += aux1[(size_t)row * auxld + col];
                v01 += aux1[(size_t)row * auxld + col + 1];
                v10 += aux1[(size_t)(row + 8) * auxld + col];
                v11 += aux1[(size_t)(row + 8) * auxld + col + 1];
                store_hilo(Ch, Cl, ldc, row, col, v00, v01);
                store_hilo(Ch, Cl, ldc, row + 8, col, v10, v11);
            }
        }
    }
}

// ---------------- helpers ----------------
__device__ __forceinline__ void split4(const float* vv, __nv_bfloat16* dh,
                                       __nv_bfloat16* dl, size_t o) {
#pragma unroll
    for (int x = 0; x < 4; x += 2) {
        __nv_bfloat16 h0 = __float2bfloat16(vv[x]);
        __nv_bfloat16 h1 = __float2bfloat16(vv[x + 1]);
        __nv_bfloat162 hp; hp.x = h0; hp.y = h1;
        __nv_bfloat162 lp;
        lp.x = __float2bfloat16(vv[x] - __bfloat162float(h0));
        lp.y = __float2bfloat16(vv[x + 1] - __bfloat162float(h1));
        *(__nv_bfloat162*)(dh + o + x) = hp;
        *(__nv_bfloat162*)(dl + o + x) = lp;
    }
}

__global__ __launch_bounds__(256) void fuse_cg(
    const float* __restrict__ p, __nv_bfloat16* __restrict__ ch, __nv_bfloat16* __restrict__ cl)
{
    const size_t base = ((size_t)blockIdx.x * 256 + threadIdx.x) * 4;
    float4 s = *(const float4*)(p + base);
#pragma unroll
    for (int z = 1; z < 4; z++) {
        const float4 q = *(const float4*)(p + (size_t)z * 262144 + base);
        s.x += q.x; s.y += q.y; s.z += q.z; s.w += q.w;
    }
    split4((const float*)&s, ch, cl, base);
}

__global__ __launch_bounds__(256) void fuse_m2(
    const float* __restrict__ p, const float* __restrict__ part,
    const float* __restrict__ br,
    __nv_bfloat16* __restrict__ mh, __nv_bfloat16* __restrict__ ml)
{
    const size_t base = ((size_t)blockIdx.x * 256 + threadIdx.x) * 4;
    const int n = (int)(base & 511), m = (int)(base >> 9);
    float4 s = *(const float4*)(p + base);
    const float4 q = *(const float4*)(p + 524288 + base);
    float sv[4] = {s.x + q.x, s.y + q.y, s.z + q.z, s.w + q.w};
    const float bm = br[m];
#pragma unroll
    for (int x = 0; x < 4; x++) {
        float cs = 0.f;
#pragma unroll
        for (int pp = 0; pp < 8; pp++) cs += part[pp * 512 + n + x];
        sv[x] = fmaf(bm, cs, sv[x]);
    }
    split4(sv, mh, ml, base);
}

__global__ __launch_bounds__(256) void convA(
    const float* __restrict__ mention, const float* __restrict__ Wv,
    const float* __restrict__ Wu,
    __nv_bfloat16* __restrict__ mhi, __nv_bfloat16* __restrict__ mlo,
    __nv_bfloat16* __restrict__ wvuh, __nv_bfloat16* __restrict__ wvul)
{
    const int blk = blockIdx.x, t = threadIdx.x;
    if (blk < 2048) {
        const size_t i = (size_t)blk * 1024 + t * 4;
        float4 v = *(const float4*)(mention + i);
        split4((const float*)&v, mhi, mlo, i);
    } else if (blk < 2304) {
        const int r = blk - 2048;
        const size_t si = (size_t)r * 1024 + t * 4;
        float4 v = *(const float4*)(Wv + si);
        split4((const float*)&v, wvuh, wvul, (size_t)(2 * r) * 1024 + t * 4);
    } else {
        const int r = blk - 2304;
        const size_t si = (size_t)r * 1024 + t * 4;
        float4 v = *(const float4*)(Wu + si);
        split4((const float*)&v, wvuh, wvul, (size_t)(2 * r + 1) * 1024 + t * 4);
    }
}

// convR: merged rel-stream prep (Wr, Wo2, RM transpose, colsum partials)
__global__ __launch_bounds__(256) void convR(
    const float* __restrict__ Wr, const float* __restrict__ Wo,
    const float* __restrict__ RM,
    __nv_bfloat16* __restrict__ wrh, __nv_bfloat16* __restrict__ wrl,
    __nv_bfloat16* __restrict__ wo2h, __nv_bfloat16* __restrict__ wo2l,
    __nv_bfloat16* __restrict__ rmth, __nv_bfloat16* __restrict__ rmtl,
    float* __restrict__ part)
{
    const int blk = blockIdx.x, t = threadIdx.x;
    if (blk < 512) {
        const size_t i = (size_t)blk * 1024 + t * 4;
        float4 v = *(const float4*)(Wr + i);
        split4((const float*)&v, wrh, wrl, i);
    } else if (blk < 1024) {
        const size_t li = (size_t)(blk - 512) * 1024 + t * 4;
        const int r = (int)(li >> 9), c = (int)(li & 511);
        float4 v = *(const float4*)(Wo + 1024 + (size_t)r * 1536 + c);
        split4((const float*)&v, wo2h, wo2l, (size_t)r * 512 + c);
    } else if (blk < 1536) {
        __shared__ float tb[32][33];
        const int local = blk - 1024;
        const int k0 = (local & 31) * 32, i0 = (local >> 5) * 32;
        const int tx = t & 31, ty = t >> 5;
#pragma unroll
        for (int q = 0; q < 4; q++)
            tb[ty + q * 8][tx] = RM[(size_t)(k0 + ty + q * 8) * 512 + i0 + tx];
        __syncthreads();
#pragma unroll
        for (int q = 0; q < 4; q++) {
            float v = tb[tx][ty + q * 8];
            size_t o = (size_t)(i0 + ty + q * 8) * 1024 + k0 + tx;
            __nv_bfloat16 h = __float2bfloat16(v);
            rmth[o] = h;
            rmtl[o] = __float2bfloat16(v - __bfloat162float(h));
        }
    } else {
        const int local = blk - 1536;
        const int p = local >> 1;
        const int j = (local & 1) * 256 + t;
        float s = 0.f;
#pragma unroll 4
        for (int r = 0; r < 128; r++) s += RM[(size_t)(p * 128 + r) * 512 + j];
        part[p * 512 + j] = s;
    }
}

__global__ __launch_bounds__(256) void pool2(
    const float* __restrict__ mention, const int* __restrict__ ent,
    const int* __restrict__ msk, const float* __restrict__ g16,
    const float* __restrict__ ba,
    __nv_bfloat16* __restrict__ Eh, __nv_bfloat16* __restrict__ El)
{
    const int be = blockIdx.x, b = be >> 7, tid = threadIdx.x;
    __shared__ float w[16];
    __shared__ int idx[16];
    if (tid < 16) {
        const int id = ent[(size_t)be * 16 + tid];
        idx[tid] = id;
        if (msk[(size_t)be * 16 + tid]) {
            float gs = ba[0];
            const int row = b * 256 + id;
#pragma unroll
            for (int cb = 0; cb < 16; cb++) gs += g16[cb * 2048 + row];
            w[tid] = gs;
        } else {
            w[tid] = -1e25f;
        }
    }
    __syncthreads();
    if (tid == 0) {
        float mx = -INFINITY;
#pragma unroll
        for (int k = 0; k < 16; k++) mx = fmaxf(mx, w[k]);
        float e[16], sum = 0.f;
#pragma unroll
        for (int k = 0; k < 16; k++) { e[k] = expf(w[k] - mx); sum += e[k]; }
        const float inv = 1.f / sum;
#pragma unroll
        for (int k = 0; k < 16; k++) w[k] = e[k] * inv;
    }
    __syncthreads();
    const float* mb = mention + (size_t)b * 256 * 1024;
    const int h0 = tid * 4;
    float4 acc = make_float4(0.f, 0.f, 0.f, 0.f);
#pragma unroll
    for (int k = 0; k < 16; k++) {
        const float4 v = *(const float4*)(mb + (size_t)idx[k] * 1024 + h0);
        const float wk = w[k];
        acc.x = fmaf(wk, v.x, acc.x);
        acc.y = fmaf(wk, v.y, acc.y);
        acc.z = fmaf(wk, v.z, acc.z);
        acc.w = fmaf(wk, v.w, acc.w);
    }
    split4((const float*)&acc, Eh, El, (size_t)be * 1024 + h0);
}

// ---------------- launch ----------------
extern "C" void kernel_launch(void* const* d_in, const int* in_sizes, int n_in,
                              void* d_out, int out_size)
{
    const float* mention  = (const float*)d_in[0];
    const int*   entities = (const int*)d_in[1];
    const int*   masks    = (const int*)d_in[2];
    const float* RM       = (const float*)d_in[3];
    const float* Wv       = (const float*)d_in[4];
    const float* bv       = (const float*)d_in[5];
    const float* Wu       = (const float*)d_in[6];
    const float* bu       = (const float*)d_in[7];
    const float* Wa       = (const float*)d_in[8];
    const float* ba       = (const float*)d_in[9];
    const float* Wr       = (const float*)d_in[10];
    const float* br       = (const float*)d_in[11];
    const float* Wo       = (const float*)d_in[12];
    const float* bo       = (const float*)d_in[13];
    float* out = (float*)d_out;

    __nv_bfloat16 *mhi, *mlo, *wvuh, *wvul, *rmth, *rmtl, *wrh, *wrl, *wo2h, *wo2l;
    __nv_bfloat16 *cgh, *cgl, *m2h, *m2l, *wth, *wtl, *eh, *el;
    float *parena, *g16, *part;
    cudaGetSymbolAddress((void**)&mhi, g_mhi);   cudaGetSymbolAddress((void**)&mlo, g_mlo);
    cudaGetSymbolAddress((void**)&wvuh, g_wvuh); cudaGetSymbolAddress((void**)&wvul, g_wvul);
    cudaGetSymbolAddress((void**)&rmth, g_rmth); cudaGetSymbolAddress((void**)&rmtl, g_rmtl);
    cudaGetSymbolAddress((void**)&wrh, g_wrh);   cudaGetSymbolAddress((void**)&wrl, g_wrl);
    cudaGetSymbolAddress((void**)&wo2h, g_wo2h); cudaGetSymbolAddress((void**)&wo2l, g_wo2l);
    cudaGetSymbolAddress((void**)&cgh, g_cgh);   cudaGetSymbolAddress((void**)&cgl, g_cgl);
    cudaGetSymbolAddress((void**)&m2h, g_m2h);   cudaGetSymbolAddress((void**)&m2l, g_m2l);
    cudaGetSymbolAddress((void**)&wth, g_wth);   cudaGetSymbolAddress((void**)&wtl, g_wtl);
    cudaGetSymbolAddress((void**)&eh, g_eh);     cudaGetSymbolAddress((void**)&el, g_el);
    cudaGetSymbolAddress((void**)&parena, g_P);
    cudaGetSymbolAddress((void**)&g16, g_g16);
    cudaGetSymbolAddress((void**)&part, g_part);

    cudaFuncSetAttribute(gemm_bf16x3<EP_SCORE>, cudaFuncAttributeMaxDynamicSharedMemorySize, SMEM_GEMM);
    cudaFuncSetAttribute(gemm_bf16x3<EP_PART>,  cudaFuncAttributeMaxDynamicSharedMemorySize, SMEM_GEMM);
    cudaFuncSetAttribute(gemm_bf16x3<EP_WEFFT>, cudaFuncAttributeMaxDynamicSharedMemorySize, SMEM_GEMM);
    cudaFuncSetAttribute(gemm_bf16x3<EP_OUT>,   cudaFuncAttributeMaxDynamicSharedMemorySize, SMEM_GEMM);

    cudaEventRecord(e_fork, 0);
    cudaStreamWaitEvent(s_rel, e_fork, 0);

    // ---- relation chain (s_rel) ----
    convR<<<1552, 256, 0, s_rel>>>(Wr, Wo, RM, wrh, wrl, wo2h, wo2l, rmth, rmtl, part);
    gemm_bf16x3<EP_PART><<<dim3(8, 4, 4), 512, SMEM_GEMM, s_rel>>>(
        rmth, rmtl, 1024, rmth, rmtl, 1024, 256, parena, nullptr, nullptr, 512,
        nullptr, nullptr, nullptr, 0, (size_t)512 * 512);
    fuse_cg<<<256, 256, 0, s_rel>>>(parena, cgh, cgl);
    gemm_bf16x3<EP_PART><<<dim3(8, 8, 2), 512, SMEM_GEMM, s_rel>>>(
        wrh, wrl, 512, cgh, cgl, 512, 256, parena, nullptr, nullptr, 512,
        nullptr, nullptr, nullptr, 0, (size_t)1024 * 512);
    fuse_m2<<<512, 256, 0, s_rel>>>(parena, part, br, m2h, m2l);
    gemm_bf16x3<EP_WEFFT><<<dim3(16, 8), 512, SMEM_GEMM, s_rel>>>(
        wo2h, wo2l, 512, m2h, m2l, 512, 512, nullptr, wth, wtl, 1024,
        Wo, nullptr, nullptr, 1536, 0);
    cudaEventRecord(e_rel, s_rel);

    // ---- attention chain (legacy stream) ----
    convA<<<2560, 256>>>(mention, Wv, Wu, mhi, mlo, wvuh, wvul);
    gemm_bf16x3<EP_SCORE><<<dim3(8, 16), 512, SMEM_GEMM>>>(
        mhi, mlo, 1024, wvuh, wvul, 1024, 1024, g16, nullptr, nullptr, 0,
        bv, bu, Wa, 0, 0);
    pool2<<<1024, 256>>>(mention, entities, masks, g16, ba, eh, el);

    cudaStreamWaitEvent(0, e_rel, 0);
    gemm_bf16x3<EP_OUT><<<dim3(16, 8), 512, SMEM_GEMM>>>(
        eh, el, 1024, wth, wtl, 1024, 1024, out, nullptr, nullptr, 1024,
        bo, nullptr, nullptr, 0, 0);
}

// round 11
// speedup vs baseline: 1.2698x; 1.2698x over previous
#include <cuda_runtime.h>
#include <cuda_bf16.h>
#include <cuda_fp16.h>
#include <stdint.h>
#include <math.h>

// ============================================================================
// Shapes: B=8, M=256, E=128, K=16, H=1024, A=256, R=1024, RMS=512
//   P = mention @ Wvu^T (fp16 2-term), score fused into epilogue
//   E = softmax-pooled mention rows (fp16)
//   Cg = RMT@RMT^T (bf16x3, split-K4) ; M2 = Wr Cg + br(x)colsum (bf16x3, split-K2)
//   WT = Wo2 M2^T + Wo1 (fp16 2-term) ; out = E WT^T + bo (fp16 2-term)
// 2-term scheme: C = Ah*(Bh+Bl), A rounded to fp16 (err ~2^-12), B split hi/lo.
// 3-term scheme: bf16x3 hi/lo (hh+hl+lh), as in the proven 98.5us build.
// Block 128x64, BK=64, 256 threads (8 warps 4x2, 32x32 warp tiles), 3-stage
// cp.async, register double-buffered fragments.
// ============================================================================

__device__ __half         g_mhi[2048*1024];
__device__ __half         g_wvuh[512*1024], g_wvul[512*1024];   // interleaved v/u rows
__device__ __nv_bfloat16  g_rmth[512*1024], g_rmtl[512*1024];
__device__ __nv_bfloat16  g_wrh[1024*512],  g_wrl[1024*512];
__device__ __half         g_wo2h[1024*512];
__device__ __nv_bfloat16  g_cgh[512*512],   g_cgl[512*512];
__device__ __half         g_m2h[1024*512],  g_m2l[1024*512];
__device__ __half         g_wth[1024*1024], g_wtl[1024*1024];
__device__ __half         g_eh[1024*1024];
__device__ float g_P[2048*512];      // split-K partial arena
__device__ float g_g16[16*2048];     // score column-block partials
__device__ float g_part[8*512];

static cudaStream_t s_rel;
static cudaEvent_t  e_fork, e_rel;
static struct StreamInit {
    StreamInit() {
        cudaStreamCreateWithFlags(&s_rel, cudaStreamNonBlocking);
        cudaEventCreateWithFlags(&e_fork, cudaEventDisableTiming);
        cudaEventCreateWithFlags(&e_rel,  cudaEventDisableTiming);
    }
} s_init;

__device__ __forceinline__ uint32_t smem_u32(const void* p) {
    uint32_t a;
    asm("{ .reg .u64 t; cvta.to.shared.u64 t, %1; cvt.u32.u64 %0, t; }" : "=r"(a) : "l"(p));
    return a;
}

#define CP16(dst, src) \
    asm volatile("cp.async.cg.shared.global [%0], [%1], 16;" :: "r"(dst), "l"(src))
#define CP_COMMIT() asm volatile("cp.async.commit_group;" ::: "memory")
#define CP_WAIT(n)  asm volatile("cp.async.wait_group %0;" :: "n"(n) : "memory")

#define LDSM4(r0, r1, r2, r3, addr) \
    asm volatile("ldmatrix.sync.aligned.m8n8.x4.shared.b16 {%0,%1,%2,%3}, [%4];" \
        : "=r"(r0), "=r"(r1), "=r"(r2), "=r"(r3) : "r"(addr))

__device__ __forceinline__ void mma_bf16(float* c, const uint32_t* a, const uint32_t* b) {
    asm volatile("mma.sync.aligned.m16n8k16.row.col.f32.bf16.bf16.f32 "
        "{%0,%1,%2,%3}, {%4,%5,%6,%7}, {%8,%9}, {%0,%1,%2,%3};"
        : "+f"(c[0]), "+f"(c[1]), "+f"(c[2]), "+f"(c[3])
        : "r"(a[0]), "r"(a[1]), "r"(a[2]), "r"(a[3]), "r"(b[0]), "r"(b[1]));
}
__device__ __forceinline__ void mma_f16(float* c, const uint32_t* a, const uint32_t* b) {
    asm volatile("mma.sync.aligned.m16n8k16.row.col.f32.f16.f16.f32 "
        "{%0,%1,%2,%3}, {%4,%5,%6,%7}, {%8,%9}, {%0,%1,%2,%3};"
        : "+f"(c[0]), "+f"(c[1]), "+f"(c[2]), "+f"(c[3])
        : "r"(a[0]), "r"(a[1]), "r"(a[2]), "r"(a[3]), "r"(b[0]), "r"(b[1]));
}

// BK=64: rows 128B, padded to 144B (rows start at bank 4r mod 32 -> conflict-free)
#define TSTRIDE 144
#define ATILEB  (128 * TSTRIDE)            // 18432
#define BTILEB  (64 * TSTRIDE)             // 9216
#define NSTAGE  3
// 3-term (bf16x3): Ah, Al, Bh, Bl
#define STAGEB3 (2 * ATILEB + 2 * BTILEB)  // 55296
#define SMEM_G3 (NSTAGE * STAGEB3)         // 165888
// 2-term (fp16): Ah, Bh, Bl
#define STAGEB2 (ATILEB + 2 * BTILEB)      // 36864
#define SMEM_G2 (NSTAGE * STAGEB2)         // 110592

enum { EP_SCORE = 0, EP_PART = 1, EP_WEFFT = 2, EP_OUT = 3 };

__device__ __forceinline__ void issue_tileA(uint32_t sdst,
        const uint16_t* __restrict__ G, int ld, int r0, int k0, int t) {
#pragma unroll
    for (int q = 0; q < 4; q++) {
        const int idx = t + (q << 8);
        const int r = idx >> 3, ch = idx & 7;
        CP16(sdst + r * TSTRIDE + ch * 16,
             G + (size_t)(r0 + r) * ld + k0 + ch * 8);
    }
}
__device__ __forceinline__ void issue_tileB(uint32_t sdst,
        const uint16_t* __restrict__ G, int ld, int r0, int k0, int t) {
#pragma unroll
    for (int q = 0; q < 2; q++) {
        const int idx = t + (q << 8);
        const int r = idx >> 3, ch = idx & 7;
        CP16(sdst + r * TSTRIDE + ch * 16,
             G + (size_t)(r0 + r) * ld + k0 + ch * 8);
    }
}

__device__ __forceinline__ void store_hilo_h(__half* Ch, __half* Cl,
        int ldc, int row, int col, float v0, float v1) {
    __half h0 = __float2half(v0);
    __half h1 = __float2half(v1);
    __half2 hp; hp.x = h0; hp.y = h1;
    __half2 lp;
    lp.x = __float2half(v0 - __half2float(h0));
    lp.y = __float2half(v1 - __half2float(h1));
    *(__half2*)(Ch + (size_t)row * ldc + col) = hp;
    *(__half2*)(Cl + (size_t)row * ldc + col) = lp;
}

template <int EPI>
__global__ __launch_bounds__(256, 1)
void gemm_mix(
    const uint16_t* __restrict__ Ah, const uint16_t* __restrict__ Al, int lda,
    const uint16_t* __restrict__ Bh, const uint16_t* __restrict__ Bl, int ldb,
    int Kper,
    float* __restrict__ Cf, __half* __restrict__ Ch, __half* __restrict__ Cl,
    int ldc,
    const float* __restrict__ aux1, const float* __restrict__ aux2,
    const float* __restrict__ aux3, int auxld, size_t partStride)
{
    constexpr bool TWO = (EPI == EP_SCORE || EPI == EP_WEFFT || EPI == EP_OUT);
    constexpr int STB = TWO ? STAGEB2 : STAGEB3;
    constexpr uint32_t OBH = TWO ? (uint32_t)ATILEB : (uint32_t)(2 * ATILEB);
    constexpr uint32_t OBL = OBH + (uint32_t)BTILEB;

    extern __shared__ __align__(128) char sm[];
    const uint32_t sbase = smem_u32(sm);
    const int t = threadIdx.x, lane = t & 31, wid = t >> 5;
    const int wm = wid >> 1, wn = wid & 1;   // 4x2 grid, warp tile 32x32
    const int m0 = blockIdx.y * 128, n0 = blockIdx.x * 64;
    const int Koff = blockIdx.z * Kper;
    const int nch = Kper >> 6;

    float acc[2][4][4] = {};
    uint32_t fAh[2][2][4], fBh[2][4][2], fBl[2][4][2];
    uint32_t fAl[2][2][4];   // used only by 3-term

#pragma unroll
    for (int c = 0; c < 2; c++) {
        const uint32_t sb = sbase + c * STB;
        issue_tileA(sb, Ah, lda, m0, Koff + c * 64, t);
        if (!TWO) issue_tileA(sb + ATILEB, Al, lda, m0, Koff + c * 64, t);
        issue_tileB(sb + OBH, Bh, ldb, n0, Koff + c * 64, t);
        issue_tileB(sb + OBL, Bl, ldb, n0, Koff + c * 64, t);
        CP_COMMIT();
    }

    const uint32_t a_off = (uint32_t)((lane & 15) * TSTRIDE + (lane >> 4) * 16)
                         + (uint32_t)(wm * 32 * TSTRIDE);
    const uint32_t b_off = (uint32_t)(((lane & 7) + ((lane >> 4) & 1) * 8) * TSTRIDE
                                      + ((lane >> 3) & 1) * 16)
                         + (uint32_t)(wn * 32 * TSTRIDE);

    for (int c = 0; c < nch; c++) {
        CP_WAIT(1);
        __syncthreads();
        if (c + 2 < nch) {
            const uint32_t sb = sbase + ((c + 2) % NSTAGE) * STB;
            issue_tileA(sb, Ah, lda, m0, Koff + (c + 2) * 64, t);
            if (!TWO) issue_tileA(sb + ATILEB, Al, lda, m0, Koff + (c + 2) * 64, t);
            issue_tileB(sb + OBH, Bh, ldb, n0, Koff + (c + 2) * 64, t);
            issue_tileB(sb + OBL, Bl, ldb, n0, Koff + (c + 2) * 64, t);
        }
        CP_COMMIT();

        const uint32_t sb = sbase + (c % NSTAGE) * STB;
        const uint32_t sAh = sb + a_off;
        const uint32_t sAl = sb + ATILEB + a_off;   // 3-term only
        const uint32_t sBh = sb + OBH + b_off;
        const uint32_t sBl = sb + OBL + b_off;

        // k-step 0 fragments
#pragma unroll
        for (int mi = 0; mi < 2; mi++) {
            const uint32_t ao = mi * 16 * TSTRIDE;
            LDSM4(fAh[0][mi][0], fAh[0][mi][1], fAh[0][mi][2], fAh[0][mi][3], sAh + ao);
            if (!TWO) LDSM4(fAl[0][mi][0], fAl[0][mi][1], fAl[0][mi][2], fAl[0][mi][3], sAl + ao);
        }
#pragma unroll
        for (int np = 0; np < 2; np++) {
            const uint32_t bo = np * 16 * TSTRIDE;
            LDSM4(fBh[0][np*2][0], fBh[0][np*2][1], fBh[0][np*2+1][0], fBh[0][np*2+1][1], sBh + bo);
            LDSM4(fBl[0][np*2][0], fBl[0][np*2][1], fBl[0][np*2+1][0], fBl[0][np*2+1][1], sBl + bo);
        }

#pragma unroll
        for (int ks = 0; ks < 4; ks++) {
            const int cur = ks & 1, nxt = cur ^ 1;
            if (ks < 3) {   // prefetch next k-step fragments before MMAs
                const uint32_t ko = (uint32_t)(ks + 1) * 32;
#pragma unroll
                for (int mi = 0; mi < 2; mi++) {
                    const uint32_t ao = mi * 16 * TSTRIDE + ko;
                    LDSM4(fAh[nxt][mi][0], fAh[nxt][mi][1], fAh[nxt][mi][2], fAh[nxt][mi][3], sAh + ao);
                    if (!TWO) LDSM4(fAl[nxt][mi][0], fAl[nxt][mi][1], fAl[nxt][mi][2], fAl[nxt][mi][3], sAl + ao);
                }
#pragma unroll
                for (int np = 0; np < 2; np++) {
                    const uint32_t bo = np * 16 * TSTRIDE + ko;
                    LDSM4(fBh[nxt][np*2][0], fBh[nxt][np*2][1], fBh[nxt][np*2+1][0], fBh[nxt][np*2+1][1], sBh + bo);
                    LDSM4(fBl[nxt][np*2][0], fBl[nxt][np*2][1], fBl[nxt][np*2+1][0], fBl[nxt][np*2+1][1], sBl + bo);
                }
            }
            if (TWO) {
#pragma unroll
                for (int mi = 0; mi < 2; mi++)
#pragma unroll
                    for (int nj = 0; nj < 4; nj++)
                        mma_f16(acc[mi][nj], fAh[cur][mi], fBh[cur][nj]);
#pragma unroll
                for (int mi = 0; mi < 2; mi++)
#pragma unroll
                    for (int nj = 0; nj < 4; nj++)
                        mma_f16(acc[mi][nj], fAh[cur][mi], fBl[cur][nj]);
            } else {
#pragma unroll
                for (int mi = 0; mi < 2; mi++)
#pragma unroll
                    for (int nj = 0; nj < 4; nj++)
                        mma_bf16(acc[mi][nj], fAh[cur][mi], fBh[cur][nj]);
#pragma unroll
                for (int mi = 0; mi < 2; mi++)
#pragma unroll
                    for (int nj = 0; nj < 4; nj++)
                        mma_bf16(acc[mi][nj], fAh[cur][mi], fBl[cur][nj]);
#pragma unroll
                for (int mi = 0; mi < 2; mi++)
#pragma unroll
                    for (int nj = 0; nj < 4; nj++)
                        mma_bf16(acc[mi][nj], fAl[cur][mi], fBh[cur][nj]);
            }
        }
    }

    __syncthreads();

    const int g = lane >> 2, tq = lane & 3;

    if (EPI == EP_SCORE) {
        float pl[2];
#pragma unroll
        for (int mi = 0; mi < 2; mi++) {
            float p0 = 0.f, p8 = 0.f;
#pragma unroll
            for (int nj = 0; nj < 4; nj++) {
                const int C = n0 + wn * 32 + nj * 8 + tq * 2;
                const int a = C >> 1;
                const float bva = aux1[a], bua = aux2[a], waa = aux3[a];
                {
                    float v = tanhf(acc[mi][nj][0] + bva);
                    float u = acc[mi][nj][1] + bua;
                    u = 1.f / (1.f + __expf(-u));
                    p0 = fmaf(v * u, waa, p0);
                }
                {
                    float v = tanhf(acc[mi][nj][2] + bva);
                    float u = acc[mi][nj][3] + bua;
                    u = 1.f / (1.f + __expf(-u));
                    p8 = fmaf(v * u, waa, p8);
                }
            }
            pl[0] = p0; pl[1] = p8;
#pragma unroll
            for (int o = 1; o <= 2; o <<= 1) {
                pl[0] += __shfl_xor_sync(0xffffffffu, pl[0], o);
                pl[1] += __shfl_xor_sync(0xffffffffu, pl[1], o);
            }
            if (tq == 0) {
                const int cb = blockIdx.x * 2 + wn;
                const int row = m0 + wm * 32 + mi * 16 + g;
                Cf[(size_t)cb * 2048 + row] = pl[0];
                Cf[(size_t)cb * 2048 + row + 8] = pl[1];
            }
        }
        return;
    }

#pragma unroll
    for (int mi = 0; mi < 2; mi++) {
#pragma unroll
        for (int nj = 0; nj < 4; nj++) {
            const int row = m0 + wm * 32 + mi * 16 + g;
            const int col = n0 + wn * 32 + nj * 8 + tq * 2;
            float v00 = acc[mi][nj][0], v01 = acc[mi][nj][1];
            float v10 = acc[mi][nj][2], v11 = acc[mi][nj][3];
            if (EPI == EP_PART) {
                float* dst = Cf + blockIdx.z * partStride;
                *(float2*)(dst + (size_t)row * ldc + col) = make_float2(v00, v01);
                *(float2*)(dst + (size_t)(row + 8) * ldc + col) = make_float2(v10, v11);
            } else if (EPI == EP_OUT) {
                const float b0 = aux1[col], b1 = aux1[col + 1];
                *(float2*)(Cf + (size_t)row * ldc + col) = make_float2(v00 + b0, v01 + b1);
                *(float2*)(Cf + (size_t)(row + 8) * ldc + col) = make_float2(v10 + b0, v11 + b1);
            } else {  // EP_WEFFT: + Wo1, write fp16 hi/lo
                v00 += aux1[(size_t)row * auxld + col];
                v01 += aux1[(size_t)row * auxld + col + 1];
                v10 += aux1[(size_t)(row + 8) * auxld + col];
                v11 += aux1[(size_t)(row + 8) * auxld + col + 1];
                store_hilo_h(Ch, Cl, ldc, row, col, v00, v01);
                store_hilo_h(Ch, Cl, ldc, row + 8, col, v10, v11);
            }
        }
    }
}

// ---------------- helpers ----------------
__device__ __forceinline__ void split4_bf(const float* vv, __nv_bfloat16* dh,
                                          __nv_bfloat16* dl, size_t o) {
#pragma unroll
    for (int x = 0; x < 4; x += 2) {
        __nv_bfloat16 h0 = __float2bfloat16(vv[x]);
        __nv_bfloat16 h1 = __float2bfloat16(vv[x + 1]);
        __nv_bfloat162 hp; hp.x = h0; hp.y = h1;
        __nv_bfloat162 lp;
        lp.x = __float2bfloat16(vv[x] - __bfloat162float(h0));
        lp.y = __float2bfloat16(vv[x + 1] - __bfloat162float(h1));
        *(__nv_bfloat162*)(dh + o + x) = hp;
        *(__nv_bfloat162*)(dl + o + x) = lp;
    }
}
__device__ __forceinline__ void split4_h(const float* vv, __half* dh,
                                         __half* dl, size_t o) {
#pragma unroll
    for (int x = 0; x < 4; x += 2) {
        __half h0 = __float2half(vv[x]);
        __half h1 = __float2half(vv[x + 1]);
        __half2 hp; hp.x = h0; hp.y = h1;
        __half2 lp;
        lp.x = __float2half(vv[x] - __half2float(h0));
        lp.y = __float2half(vv[x + 1] - __half2float(h1));
        *(__half2*)(dh + o + x) = hp;
        *(__half2*)(dl + o + x) = lp;
    }
}
__device__ __forceinline__ void round4_h(const float* vv, __half* dh, size_t o) {
#pragma unroll
    for (int x = 0; x < 4; x += 2) {
        __half2 hp; hp.x = __float2half(vv[x]); hp.y = __float2half(vv[x + 1]);
        *(__half2*)(dh + o + x) = hp;
    }
}

__global__ __launch_bounds__(256) void fuse_cg(
    const float* __restrict__ p, __nv_bfloat16* __restrict__ ch, __nv_bfloat16* __restrict__ cl)
{
    const size_t base = ((size_t)blockIdx.x * 256 + threadIdx.x) * 4;
    float4 s = *(const float4*)(p + base);
#pragma unroll
    for (int z = 1; z < 4; z++) {
        const float4 q = *(const float4*)(p + (size_t)z * 262144 + base);
        s.x += q.x; s.y += q.y; s.z += q.z; s.w += q.w;
    }
    split4_bf((const float*)&s, ch, cl, base);
}

__global__ __launch_bounds__(256) void fuse_m2(
    const float* __restrict__ p, const float* __restrict__ part,
    const float* __restrict__ br,
    __half* __restrict__ mh, __half* __restrict__ ml)
{
    const size_t base = ((size_t)blockIdx.x * 256 + threadIdx.x) * 4;
    const int n = (int)(base & 511), m = (int)(base >> 9);
    float4 s = *(const float4*)(p + base);
    const float4 q = *(const float4*)(p + 524288 + base);
    float sv[4] = {s.x + q.x, s.y + q.y, s.z + q.z, s.w + q.w};
    const float bm = br[m];
#pragma unroll
    for (int x = 0; x < 4; x++) {
        float cs = 0.f;
#pragma unroll
        for (int pp = 0; pp < 8; pp++) cs += part[pp * 512 + n + x];
        sv[x] = fmaf(bm, cs, sv[x]);
    }
    split4_h(sv, mh, ml, base);
}

// convA: mention (2048 blks, fp16 round) | Wv -> interleaved even rows | Wu -> odd
__global__ __launch_bounds__(256) void convA(
    const float* __restrict__ mention, const float* __restrict__ Wv,
    const float* __restrict__ Wu,
    __half* __restrict__ mhi,
    __half* __restrict__ wvuh, __half* __restrict__ wvul)
{
    const int blk = blockIdx.x, t = threadIdx.x;
    if (blk < 2048) {
        const size_t i = (size_t)blk * 1024 + t * 4;
        float4 v = *(const float4*)(mention + i);
        round4_h((const float*)&v, mhi, i);
    } else if (blk < 2304) {
        const int r = blk - 2048;
        const size_t si = (size_t)r * 1024 + t * 4;
        float4 v = *(const float4*)(Wv + si);
        split4_h((const float*)&v, wvuh, wvul, (size_t)(2 * r) * 1024 + t * 4);
    } else {
        const int r = blk - 2304;
        const size_t si = (size_t)r * 1024 + t * 4;
        float4 v = *(const float4*)(Wu + si);
        split4_h((const float*)&v, wvuh, wvul, (size_t)(2 * r + 1) * 1024 + t * 4);
    }
}

// convR: rel-stream prep (Wr bf16 hi/lo, Wo2 fp16 round, RM transpose bf16, colsum)
__global__ __launch_bounds__(256) void convR(
    const float* __restrict__ Wr, const float* __restrict__ Wo,
    const float* __restrict__ RM,
    __nv_bfloat16* __restrict__ wrh, __nv_bfloat16* __restrict__ wrl,
    __half* __restrict__ wo2h,
    __nv_bfloat16* __restrict__ rmth, __nv_bfloat16* __restrict__ rmtl,
    float* __restrict__ part)
{
    const int blk = blockIdx.x, t = threadIdx.x;
    if (blk < 512) {
        const size_t i = (size_t)blk * 1024 + t * 4;
        float4 v = *(const float4*)(Wr + i);
        split4_bf((const float*)&v, wrh, wrl, i);
    } else if (blk < 1024) {
        const size_t li = (size_t)(blk - 512) * 1024 + t * 4;
        const int r = (int)(li >> 9), c = (int)(li & 511);
        float4 v = *(const float4*)(Wo + 1024 + (size_t)r * 1536 + c);
        round4_h((const float*)&v, wo2h, (size_t)r * 512 + c);
    } else if (blk < 1536) {
        __shared__ float tb[32][33];
        const int local = blk - 1024;
        const int k0 = (local & 31) * 32, i0 = (local >> 5) * 32;
        const int tx = t & 31, ty = t >> 5;
#pragma unroll
        for (int q = 0; q < 4; q++)
            tb[ty + q * 8][tx] = RM[(size_t)(k0 + ty + q * 8) * 512 + i0 + tx];
        __syncthreads();
#pragma unroll
        for (int q = 0; q < 4; q++) {
            float v = tb[tx][ty + q * 8];
            size_t o = (size_t)(i0 + ty + q * 8) * 1024 + k0 + tx;
            __nv_bfloat16 h = __float2bfloat16(v);
            rmth[o] = h;
            rmtl[o] = __float2bfloat16(v - __bfloat162float(h));
        }
    } else {
        const int local = blk - 1536;
        const int p = local >> 1;
        const int j = (local & 1) * 256 + t;
        float s = 0.f;
#pragma unroll 4
        for (int r = 0; r < 128; r++) s += RM[(size_t)(p * 128 + r) * 512 + j];
        part[p * 512 + j] = s;
    }
}

__global__ __launch_bounds__(256) void pool2(
    const float* __restrict__ mention, const int* __restrict__ ent,
    const int* __restrict__ msk, const float* __restrict__ g16,
    const float* __restrict__ ba,
    __half* __restrict__ Eh)
{
    const int be = blockIdx.x, b = be >> 7, tid = threadIdx.x;
    __shared__ float w[16];
    __shared__ int idx[16];
    if (tid < 16) {
        const int id = ent[(size_t)be * 16 + tid];
        idx[tid] = id;
        if (msk[(size_t)be * 16 + tid]) {
            float gs = ba[0];
            const int row = b * 256 + id;
#pragma unroll
            for (int cb = 0; cb < 16; cb++) gs += g16[cb * 2048 + row];
            w[tid] = gs;
        } else {
            w[tid] = -1e25f;
        }
    }
    __syncthreads();
    if (tid == 0) {
        float mx = -INFINITY;
#pragma unroll
        for (int k = 0; k < 16; k++) mx = fmaxf(mx, w[k]);
        float e[16], sum = 0.f;
#pragma unroll
        for (int k = 0; k < 16; k++) { e[k] = expf(w[k] - mx); sum += e[k]; }
        const float inv = 1.f / sum;
#pragma unroll
        for (int k = 0; k < 16; k++) w[k] = e[k] * inv;
    }
    __syncthreads();
    const float* mb = mention + (size_t)b * 256 * 1024;
    const int h0 = tid * 4;
    float4 acc = make_float4(0.f, 0.f, 0.f, 0.f);
#pragma unroll
    for (int k = 0; k < 16; k++) {
        const float4 v = *(const float4*)(mb + (size_t)idx[k] * 1024 + h0);
        const float wk = w[k];
        acc.x = fmaf(wk, v.x, acc.x);
        acc.y = fmaf(wk, v.y, acc.y);
        acc.z = fmaf(wk, v.z, acc.z);
        acc.w = fmaf(wk, v.w, acc.w);
    }
    round4_h((const float*)&acc, Eh, (size_t)be * 1024 + h0);
}

// ---------------- launch ----------------
extern "C" void kernel_launch(void* const* d_in, const int* in_sizes, int n_in,
                              void* d_out, int out_size)
{
    const float* mention  = (const float*)d_in[0];
    const int*   entities = (const int*)d_in[1];
    const int*   masks    = (const int*)d_in[2];
    const float* RM       = (const float*)d_in[3];
    const float* Wv       = (const float*)d_in[4];
    const float* bv       = (const float*)d_in[5];
    const float* Wu       = (const float*)d_in[6];
    const float* bu       = (const float*)d_in[7];
    const float* Wa       = (const float*)d_in[8];
    const float* ba       = (const float*)d_in[9];
    const float* Wr       = (const float*)d_in[10];
    const float* br       = (const float*)d_in[11];
    const float* Wo       = (const float*)d_in[12];
    const float* bo       = (const float*)d_in[13];
    float* out = (float*)d_out;

    __half *mhi, *wvuh, *wvul, *wo2h, *m2h, *m2l, *wth, *wtl, *eh;
    __nv_bfloat16 *rmth, *rmtl, *wrh, *wrl, *cgh, *cgl;
    float *parena, *g16, *part;
    cudaGetSymbolAddress((void**)&mhi, g_mhi);
    cudaGetSymbolAddress((void**)&wvuh, g_wvuh); cudaGetSymbolAddress((void**)&wvul, g_wvul);
    cudaGetSymbolAddress((void**)&rmth, g_rmth); cudaGetSymbolAddress((void**)&rmtl, g_rmtl);
    cudaGetSymbolAddress((void**)&wrh, g_wrh);   cudaGetSymbolAddress((void**)&wrl, g_wrl);
    cudaGetSymbolAddress((void**)&wo2h, g_wo2h);
    cudaGetSymbolAddress((void**)&cgh, g_cgh);   cudaGetSymbolAddress((void**)&cgl, g_cgl);
    cudaGetSymbolAddress((void**)&m2h, g_m2h);   cudaGetSymbolAddress((void**)&m2l, g_m2l);
    cudaGetSymbolAddress((void**)&wth, g_wth);   cudaGetSymbolAddress((void**)&wtl, g_wtl);
    cudaGetSymbolAddress((void**)&eh, g_eh);
    cudaGetSymbolAddress((void**)&parena, g_P);
    cudaGetSymbolAddress((void**)&g16, g_g16);
    cudaGetSymbolAddress((void**)&part, g_part);

    cudaFuncSetAttribute(gemm_mix<EP_SCORE>, cudaFuncAttributeMaxDynamicSharedMemorySize, SMEM_G2);
    cudaFuncSetAttribute(gemm_mix<EP_PART>,  cudaFuncAttributeMaxDynamicSharedMemorySize, SMEM_G3);
    cudaFuncSetAttribute(gemm_mix<EP_WEFFT>, cudaFuncAttributeMaxDynamicSharedMemorySize, SMEM_G2);
    cudaFuncSetAttribute(gemm_mix<EP_OUT>,   cudaFuncAttributeMaxDynamicSharedMemorySize, SMEM_G2);

    cudaEventRecord(e_fork, 0);
    cudaStreamWaitEvent(s_rel, e_fork, 0);

    // ---- relation chain (s_rel) ----
    convR<<<1552, 256, 0, s_rel>>>(Wr, Wo, RM, wrh, wrl, wo2h, rmth, rmtl, part);
    // Cg partials: bf16x3 split-K4
    gemm_mix<EP_PART><<<dim3(8, 4, 4), 256, SMEM_G3, s_rel>>>(
        (const uint16_t*)rmth, (const uint16_t*)rmtl, 1024,
        (const uint16_t*)rmth, (const uint16_t*)rmtl, 1024, 256,
        parena, nullptr, nullptr, 512, nullptr, nullptr, nullptr, 0, (size_t)512 * 512);
    fuse_cg<<<256, 256, 0, s_rel>>>(parena, cgh, cgl);
    // M2 partials: bf16x3 split-K2 (Cg symmetric)
    gemm_mix<EP_PART><<<dim3(8, 8, 2), 256, SMEM_G3, s_rel>>>(
        (const uint16_t*)wrh, (const uint16_t*)wrl, 512,
        (const uint16_t*)cgh, (const uint16_t*)cgl, 512, 256,
        parena, nullptr, nullptr, 512, nullptr, nullptr, nullptr, 0, (size_t)1024 * 512);
    fuse_m2<<<512, 256, 0, s_rel>>>(parena, part, br, m2h, m2l);
    // WT = Wo2(f16) @ (M2h+M2l)^T + Wo1, fp16 2-term
    gemm_mix<EP_WEFFT><<<dim3(16, 8), 256, SMEM_G2, s_rel>>>(
        (const uint16_t*)wo2h, nullptr, 512,
        (const uint16_t*)m2h, (const uint16_t*)m2l, 512, 512,
        nullptr, wth, wtl, 1024, Wo, nullptr, nullptr, 1536, 0);
    cudaEventRecord(e_rel, s_rel);

    // ---- attention chain (legacy stream) ----
    convA<<<2560, 256>>>(mention, Wv, Wu, mhi, wvuh, wvul);
    // P = mention(f16) @ (Wvuh+Wvul)^T, fp16 2-term, score fused
    gemm_mix<EP_SCORE><<<dim3(8, 16), 256, SMEM_G2>>>(
        (const uint16_t*)mhi, nullptr, 1024,
        (const uint16_t*)wvuh, (const uint16_t*)wvul, 1024, 1024,
        g16, nullptr, nullptr, 0, bv, bu, Wa, 0, 0);
    pool2<<<1024, 256>>>(mention, entities, masks, g16, ba, eh);

    cudaStreamWaitEvent(0, e_rel, 0);
    // out = E(f16) @ (WTh+WTl)^T + bo, fp16 2-term
    gemm_mix<EP_OUT><<<dim3(16, 8), 256, SMEM_G2>>>(
        (const uint16_t*)eh, nullptr, 1024,
        (const uint16_t*)wth, (const uint16_t*)wtl, 1024, 1024,
        out, nullptr, nullptr, 1024, bo, nullptr, nullptr, 0, 0);
}